// round 12
// baseline (speedup 1.0000x reference)
#include <cuda_runtime.h>
#include <cstdint>

#define Bn 16
#define Cn 80
#define Hn 128
#define Wn 128
#define HWn 16384
#define Kn 100
#define NUMD 1000
#define SEGS 32
#define HI_CAP 65536
#define CAND_CAP 262144
#define PAIR_CAP 16384
#define COMP_CAP 2048
#define HALF_CAP 512
#define SCORE_THR 0.05f
#define IOU_THR 0.5f
#define DIST_THR 0.5f
#define THR_HI 3.55f
#define STRIPS 4
#define SROWS 34                     /* 32 + 2 halo */
#define TOTB (2 * Bn * Cn * STRIPS)
#define WT 512   /* worker threads */

typedef unsigned long long u64;
typedef unsigned int u32;

#define NEG_INF __int_as_float(0xff800000)

// ---------------- device scratch (zero-initialized at load) ----------------
__device__ u64 g_hi[SEGS][HI_CAP];
__device__ int g_cnt[SEGS];
__device__ u64 g_low[SEGS][CAND_CAP];   // slow-path only
__device__ int g_cnt_low[SEGS];
__device__ u64 g_pairpos[Bn][PAIR_CAP]; // pair-sort overflow fallback

// ---------------- helpers ----------------
__device__ __forceinline__ u32 map_f(float f) {
    u32 u = __float_as_uint(f);
    return (u & 0x80000000u) ? ~u : (u | 0x80000000u);
}
__device__ __forceinline__ float sigmoidf_dev(float x) {
    if (x >= 0.f) return 1.f / (1.f + expf(-x));
    float e = expf(x);
    return e / (1.f + e);
}
__device__ __forceinline__ u64 make_key(float raw, u32 idx) {
    float s = sigmoidf_dev(raw);
    return ((u64)(__float_as_uint(s) | 0x80000000u) << 32) |
           (u64)(0xFFFFFFFFu - idx);
}

// ascending bitonic sort (fallback only)
__device__ __forceinline__ void bitonic_sort(u64* d, int n, int tid, int nt) {
    for (int k = 2; k <= n; k <<= 1) {
        for (int j = k >> 1; j > 0; j >>= 1) {
            for (int t = tid; t < n; t += nt) {
                int ixj = t ^ j;
                if (ixj > t) {
                    u64 a = d[t], b = d[ixj];
                    bool asc = ((t & k) == 0);
                    if ((a > b) == asc) { d[t] = b; d[ixj] = a; }
                }
            }
            __syncthreads();
        }
    }
}

// ================= K1: local-max via SMEM-staged 32-row strips =================
// grid: 2*B*C*4 blocks of 256 threads. Phase A: stream strip+halo into smem
// (pure LDG.128, MLP>=4). Phase B: stencil from smem (LDS + shuffles).
__global__ void __launch_bounds__(256)
k_localmax(const float* __restrict__ tl, const float* __restrict__ br) {
    __shared__ float sm[SROWS * Wn];    // 17408 B

    const int blk = blockIdx.x;
    const int strip = blk & (STRIPS - 1);
    const int plane = blk >> 2;                  // 0 .. 2*B*C-1
    const int h = plane / (Bn * Cn);
    const int rem = plane % (Bn * Cn);
    const int pb = rem / Cn;
    const int pc = rem % Cn;
    const int seg = h * Bn + pb;
    const int y0 = strip * 32;
    const float* src = (h == 0 ? tl : br) + (size_t)rem * HWn;

    const int tid = threadIdx.x;
    const int warp = tid >> 5;
    const int lane = tid & 31;
    const float4* row4 = (const float4*)src;
    float4* sm4 = (float4*)sm;

    // ---- phase A: stream strip rows (y0-1 .. y0+32) into smem ----
    const float4 ninf4 = make_float4(NEG_INF, NEG_INF, NEG_INF, NEG_INF);
    #pragma unroll
    for (int q = 0; q < 5; ++q) {
        int i = tid + q * 256;                  // 0 .. 1087
        if (i < SROWS * 32) {
            int srow = i >> 5;
            int l = i & 31;
            int pr = y0 - 1 + srow;
            sm4[srow * 32 + l] = (pr >= 0 && pr < Hn) ? row4[pr * 32 + l] : ninf4;
        }
    }
    __syncthreads();

    // ---- phase B: stencil. warp w handles plane rows y0+4w .. y0+4w+3 ----
    // smem rows needed: s = 4w .. 4w+5 (halo included in smem).
    float4 v[4];
    float4 hm[6];
    #pragma unroll
    for (int k = 0; k < 6; ++k) {
        int srow = warp * 4 + k;
        float4 vv = sm4[srow * 32 + lane];
        float left  = __shfl_up_sync(0xffffffffu, vv.w, 1);
        float right = __shfl_down_sync(0xffffffffu, vv.x, 1);
        if (lane == 0)  left  = NEG_INF;
        if (lane == 31) right = NEG_INF;
        hm[k].x = fmaxf(fmaxf(left, vv.x), vv.y);
        hm[k].y = fmaxf(fmaxf(vv.x, vv.y), vv.z);
        hm[k].z = fmaxf(fmaxf(vv.y, vv.z), vv.w);
        hm[k].w = fmaxf(fmaxf(vv.z, vv.w), right);
        if (k >= 1 && k <= 4) v[k - 1] = vv;
    }

    auto emit = [&](float val, float m, u32 idx) {
        if (val >= m) {
            int p = atomicAdd(&g_cnt[seg], 1);
            if (p < HI_CAP) g_hi[seg][p] = make_key(val, idx);
        }
    };

    #pragma unroll
    for (int r = 0; r < 4; ++r) {
        float4 w;
        w.x = fmaxf(fmaxf(fmaxf(hm[r].x, hm[r + 1].x), hm[r + 2].x), THR_HI);
        w.y = fmaxf(fmaxf(fmaxf(hm[r].y, hm[r + 1].y), hm[r + 2].y), THR_HI);
        w.z = fmaxf(fmaxf(fmaxf(hm[r].z, hm[r + 1].z), hm[r + 2].z), THR_HI);
        w.w = fmaxf(fmaxf(fmaxf(hm[r].w, hm[r + 1].w), hm[r + 2].w), THR_HI);
        bool f0 = v[r].x >= w.x;
        bool f1 = v[r].y >= w.y;
        bool f2 = v[r].z >= w.z;
        bool f3 = v[r].w >= w.w;
        bool any = f0 | f1 | f2 | f3;
        if (__ballot_sync(0xffffffffu, any)) {
            if (any) {
                int y = y0 + warp * 4 + r;
                u32 ib = (u32)(pc * HWn + y * Wn + lane * 4);
                emit(v[r].x, w.x, ib + 0);
                emit(v[r].y, w.y, ib + 1);
                emit(v[r].z, w.z, ib + 2);
                emit(v[r].w, w.w, ib + 3);
            }
        }
    }

#if __CUDA_ARCH__ >= 900
    cudaTriggerProgrammaticLaunchCompletion();
#endif
}

// ================= K2: worker =================
__global__ void __launch_bounds__(WT)
k_worker(const float* __restrict__ tl_heat, const float* __restrict__ br_heat,
         const float* __restrict__ tl_off, const float* __restrict__ br_off,
         const float* __restrict__ tl_emb, const float* __restrict__ br_emb,
         const int* __restrict__ inp_h, const int* __restrict__ inp_w,
         float* __restrict__ out) {
    __shared__ u64 comp[COMP_CAP];          // halves at [0..512) tl / [512..1024) br
    __shared__ u64 sel[2 * Kn];
    __shared__ float ts[Kn], tx[Kn], ty[Kn], te[Kn];
    __shared__ float bs_[Kn], bx[Kn], by[Kn], be[Kn];
    __shared__ int tc[Kn], bc[Kn];
    __shared__ float x1[NUMD], y1[NUMD], x2[NUMD], y2[NUMD], sc[NUMD];
    __shared__ unsigned char cl[NUMD], kp[NUMD];
    __shared__ short idxs[Kn];
    __shared__ int s_np, s_num;

    const int b = blockIdx.x;
    const int tid = threadIdx.x;
    const float wr = (float)(*inp_w) / (float)Wn;
    const float hr = (float)(*inp_h) / (float)Hn;

#if __CUDA_ARCH__ >= 900
    cudaGridDependencySynchronize();
#endif

    const int m0 = g_cnt[b];
    const int m1 = g_cnt[Bn + b];
    const bool fast0 = (m0 >= Kn && m0 <= HALF_CAP);
    const bool fast1 = (m1 >= Kn && m1 <= HALF_CAP);

    // ---------------- phase 2: per-segment top-100 ----------------
    if (fast0 && fast1) {
        const int half = tid >> 8;
        const int htid = tid & 255;
        const int seg = half * Bn + b;
        const int mhi = half ? m1 : m0;
        u64* buf = comp + half * HALF_CAP;

        for (int i = htid; i < mhi; i += 256) buf[i] = g_hi[seg][i];
        __syncthreads();

        if (htid < mhi) {
            u64 k0v = buf[htid];
            bool h1 = htid + 256 < mhi;
            u64 k1v = h1 ? buf[htid + 256] : 0ull;
            int r0c = 0, r1c = 0;
            int j = 0;
            for (; j + 4 <= mhi; j += 4) {
                u64 a = buf[j], bq = buf[j + 1], cq = buf[j + 2], dq = buf[j + 3];
                r0c += (a > k0v) + (bq > k0v) + (cq > k0v) + (dq > k0v);
                r1c += (a > k1v) + (bq > k1v) + (cq > k1v) + (dq > k1v);
            }
            for (; j < mhi; ++j) {
                u64 a = buf[j];
                r0c += (a > k0v);
                r1c += (a > k1v);
            }
            if (r0c < Kn) sel[half * Kn + r0c] = k0v;
            if (h1 && r1c < Kn) sel[half * Kn + r1c] = k1v;
        }
        __syncthreads();

        if (htid < Kn) {
            u64 key = sel[half * Kn + htid];
            u32 m = (u32)(key >> 32);
            float score = __uint_as_float(m & 0x7FFFFFFFu);
            u32 idx = 0xFFFFFFFFu - (u32)(key & 0xFFFFFFFFu);
            int cls = idx / HWn;
            int ind = idx % HWn;
            int yy = ind >> 7, xx = ind & 127;
            const float* offp = half ? br_off : tl_off;
            const float* embp = half ? br_emb : tl_emb;
            float ox = offp[((size_t)(b * 2 + 0) * HWn) + ind];
            float oy = offp[((size_t)(b * 2 + 1) * HWn) + ind];
            float em = embp[(size_t)b * HWn + ind];
            float xs = fmaxf(((float)xx + ox) * wr, 0.f);
            float ys = fmaxf(((float)yy + oy) * hr, 0.f);
            if (half == 0) {
                ts[htid] = score; tx[htid] = xs; ty[htid] = ys; te[htid] = em; tc[htid] = cls;
            } else {
                bs_[htid] = score; bx[htid] = xs; by[htid] = ys; be[htid] = em; bc[htid] = cls;
            }
        }
        __syncthreads();
    } else {
        for (int pass = 0; pass < 2; ++pass) {
            const int seg = pass * Bn + b;
            const int mhi = g_cnt[seg];

            if (mhi >= Kn && mhi <= COMP_CAP) {
                for (int i = tid; i < mhi; i += WT) comp[i] = g_hi[seg][i];
                __syncthreads();
                if (tid < mhi) {
                    u64 kv[4];
                    int rc[4];
                    #pragma unroll
                    for (int q = 0; q < 4; ++q) {
                        int p = tid + q * WT;
                        kv[q] = (p < mhi) ? comp[p] : 0ull;
                        rc[q] = 0;
                    }
                    for (int j = 0; j < mhi; ++j) {
                        u64 a = comp[j];
                        #pragma unroll
                        for (int q = 0; q < 4; ++q) rc[q] += (a > kv[q]);
                    }
                    #pragma unroll
                    for (int q = 0; q < 4; ++q) {
                        int p = tid + q * WT;
                        if (p < mhi && rc[q] < Kn) sel[rc[q]] = kv[q];
                    }
                }
                __syncthreads();
            } else {
                const float* heat = (pass ? br_heat : tl_heat) + (size_t)(b * Cn) * HWn;
                if (tid == 0) g_cnt_low[seg] = 0;
                __syncthreads();
                for (int e = tid; e < Cn * HWn; e += WT) {
                    int cc = e >> 14;
                    int ind = e & (HWn - 1);
                    int y = ind >> 7, x = ind & 127;
                    const float* pl = heat + (size_t)cc * HWn;
                    float v = pl[ind];
                    int y0b = y > 0 ? y - 1 : 0, y1b = y < 127 ? y + 1 : 127;
                    int x0 = x > 0 ? x - 1 : 0, x1b = x < 127 ? x + 1 : 127;
                    bool mx = true;
                    for (int yy = y0b; yy <= y1b; ++yy)
                        for (int xx = x0; xx <= x1b; ++xx)
                            mx &= (v >= pl[yy * Wn + xx]);
                    if (mx) {
                        int p = atomicAdd(&g_cnt_low[seg], 1);
                        if (p < CAND_CAP) g_low[seg][p] = make_key(v, (u32)(cc * HWn + ind));
                    }
                }
                __syncthreads();
                int Mc = g_cnt_low[seg];
                if (Mc > CAND_CAP) Mc = CAND_CAP;
                u64* rk = comp;
                int* ri = (int*)(comp + WT);
                for (int r = 0; r < Kn; ++r) {
                    u64 best = 0ull; int bidx = -1;
                    for (int i = tid; i < Mc; i += WT) {
                        u64 v = g_low[seg][i];
                        if (v > best) { best = v; bidx = i; }
                    }
                    rk[tid] = best; ri[tid] = bidx;
                    __syncthreads();
                    for (int s = WT / 2; s > 0; s >>= 1) {
                        if (tid < s && rk[tid + s] > rk[tid]) {
                            rk[tid] = rk[tid + s]; ri[tid] = ri[tid + s];
                        }
                        __syncthreads();
                    }
                    if (tid == 0) {
                        sel[r] = rk[0];
                        if (ri[0] >= 0) g_low[seg][ri[0]] = 0ull;
                    }
                    __syncthreads();
                }
            }

            if (tid < Kn) {
                u64 key = sel[tid];
                u32 m = (u32)(key >> 32);
                float score = __uint_as_float(m & 0x7FFFFFFFu);
                u32 idx = 0xFFFFFFFFu - (u32)(key & 0xFFFFFFFFu);
                if (key == 0ull) { idx = 0u; score = 0.f; }
                int cls = idx / HWn;
                int ind = idx % HWn;
                int yy = ind >> 7, xx = ind & 127;
                const float* offp = pass ? br_off : tl_off;
                const float* embp = pass ? br_emb : tl_emb;
                float ox = offp[((size_t)(b * 2 + 0) * HWn) + ind];
                float oy = offp[((size_t)(b * 2 + 1) * HWn) + ind];
                float em = embp[(size_t)b * HWn + ind];
                float xs = fmaxf(((float)xx + ox) * wr, 0.f);
                float ys = fmaxf(((float)yy + oy) * hr, 0.f);
                if (pass == 0) {
                    ts[tid] = score; tx[tid] = xs; ty[tid] = ys; te[tid] = em; tc[tid] = cls;
                } else {
                    bs_[tid] = score; bx[tid] = xs; by[tid] = ys; be[tid] = em; bc[tid] = cls;
                }
            }
            __syncthreads();
        }
    }

    // ---------------- phase 3: pairing + positive compaction + rank order + NMS ----------------
    if (tid == 0) s_np = 0;
    __syncthreads();

    for (int t = tid; t < Kn * Kn; t += WT) {
        int i = t / Kn, j = t % Kn;
        float scv = (ts[i] + bs_[j]) * 0.5f;
        bool neg = (tc[i] != bc[j]) || (bx[j] <= tx[i]) || (by[j] <= ty[i]) ||
                   (fabsf(te[i] - be[j]) > DIST_THR);
        if (!neg && scv > SCORE_THR) {
            int p = atomicAdd(&s_np, 1);
            u64 key = ((u64)map_f(scv) << 32) | (u64)(0xFFFFFFFFu - (u32)t);
            if (p < PAIR_CAP) g_pairpos[b][p] = key;
            if (p < COMP_CAP) comp[p] = key;
        }
    }
    __syncthreads();

    int np = s_np < PAIR_CAP ? s_np : PAIR_CAP;
    int m = np < NUMD ? np : NUMD;
    if (np > 0) {
        if (np <= COMP_CAP) {
            if (tid < np) {
                u64 kv[4];
                int rc[4];
                #pragma unroll
                for (int q = 0; q < 4; ++q) {
                    int p = tid + q * WT;
                    kv[q] = (p < np) ? comp[p] : 0ull;
                    rc[q] = 0;
                }
                for (int j = 0; j < np; ++j) {
                    u64 a = comp[j];
                    #pragma unroll
                    for (int q = 0; q < 4; ++q) rc[q] += (a > kv[q]);
                }
                #pragma unroll
                for (int q = 0; q < 4; ++q) {
                    int p = tid + q * WT;
                    if (p < np && rc[q] < NUMD) {
                        u64 key = kv[q];
                        int r = rc[q];
                        u32 mm = (u32)(key >> 32);
                        float scv = __uint_as_float(mm & 0x7FFFFFFFu);
                        u32 t = 0xFFFFFFFFu - (u32)(key & 0xFFFFFFFFu);
                        int i = t / Kn, j2 = t % Kn;
                        x1[r] = tx[i]; y1[r] = ty[i]; x2[r] = bx[j2]; y2[r] = by[j2];
                        sc[r] = scv;
                        cl[r] = (unsigned char)tc[i];
                        kp[r] = 1;
                    }
                }
            }
            __syncthreads();
        } else {
            u64* arr = g_pairpos[b];
            int n2 = 2;
            while (n2 < np) n2 <<= 1;
            for (int t = np + tid; t < n2; t += WT) arr[t] = 0ull;
            __syncthreads();
            bitonic_sort(arr, n2, tid, WT);
            for (int r = tid; r < m; r += WT) {
                u64 key = arr[n2 - 1 - r];
                u32 mm = (u32)(key >> 32);
                float scv = __uint_as_float(mm & 0x7FFFFFFFu);
                u32 t = 0xFFFFFFFFu - (u32)(key & 0xFFFFFFFFu);
                int i = t / Kn, j = t % Kn;
                x1[r] = tx[i]; y1[r] = ty[i]; x2[r] = bx[j]; y2[r] = by[j];
                sc[r] = scv;
                cl[r] = (unsigned char)tc[i];
                kp[r] = 1;
            }
            __syncthreads();
        }

        for (int i = 0; i < m; i++) {
            if (kp[i]) {
                float xi1 = x1[i], yi1 = y1[i], xi2 = x2[i], yi2 = y2[i];
                float ai = fmaxf(xi2 - xi1, 0.f) * fmaxf(yi2 - yi1, 0.f);
                unsigned char ci = cl[i];
                for (int j = i + 1 + tid; j < m; j += WT) {
                    if (kp[j] && cl[j] == ci) {
                        float aj = fmaxf(x2[j] - x1[j], 0.f) * fmaxf(y2[j] - y1[j], 0.f);
                        float iw = fmaxf(fminf(xi2, x2[j]) - fmaxf(xi1, x1[j]), 0.f);
                        float ih = fmaxf(fminf(yi2, y2[j]) - fmaxf(yi1, y1[j]), 0.f);
                        float inter = iw * ih;
                        float iou = inter / fmaxf(ai + aj - inter, 1e-6f);
                        if (iou > IOU_THR) kp[j] = 0;
                    }
                }
            }
            __syncthreads();
        }

        if (tid == 0) {
            int cnt = 0;
            for (int i = 0; i < m; i++) {
                if (kp[i]) {
                    if (cnt < Kn) idxs[cnt] = (short)i;
                    cnt++;
                }
            }
            s_num = cnt < Kn ? cnt : Kn;
        }
    } else {
        if (tid == 0) s_num = 0;
    }
    __syncthreads();

    // ---------------- output ----------------
    const int num = s_num;
    if (tid == 0) out[b] = (float)num;

    float* pb = out + Bn;
    float* ps = out + Bn + Bn * Kn * 4;
    float* pcls = out + Bn + Bn * Kn * 4 + Bn * Kn;
    for (int r = tid; r < Kn; r += WT) {
        float b0 = 0.f, b1 = 0.f, b2 = 0.f, b3 = 0.f, s = 0.f, cf = -1.0f;
        if (r < num) {
            int i = idxs[r];
            b0 = x1[i]; b1 = y1[i]; b2 = x2[i]; b3 = y2[i];
            s = sc[i]; cf = (float)cl[i];
        }
        size_t base = (size_t)(b * Kn + r);
        pb[base * 4 + 0] = b0;
        pb[base * 4 + 1] = b1;
        pb[base * 4 + 2] = b2;
        pb[base * 4 + 3] = b3;
        ps[base] = s;
        pcls[base] = cf;
    }

    // ---------------- reset counters for next graph replay ----------------
    if (tid == 0) {
        g_cnt[b] = 0;
        g_cnt[Bn + b] = 0;
    }
}

// ---------------- launch ----------------
extern "C" void kernel_launch(void* const* d_in, const int* in_sizes, int n_in,
                              void* d_out, int out_size) {
    const float* tl_heat = (const float*)d_in[0];
    const float* br_heat = (const float*)d_in[1];
    const float* tl_off  = (const float*)d_in[2];
    const float* br_off  = (const float*)d_in[3];
    const float* tl_emb  = (const float*)d_in[4];
    const float* br_emb  = (const float*)d_in[5];
    const int*   inp_h   = (const int*)d_in[6];
    const int*   inp_w   = (const int*)d_in[7];
    float* out = (float*)d_out;

    k_localmax<<<TOTB, 256>>>(tl_heat, br_heat);

    // PDL launch of the worker: its launch latency overlaps k_localmax's tail.
    cudaLaunchConfig_t cfg = {};
    cfg.gridDim = dim3(Bn, 1, 1);
    cfg.blockDim = dim3(WT, 1, 1);
    cfg.dynamicSmemBytes = 0;
    cudaLaunchAttribute attrs[1];
    attrs[0].id = cudaLaunchAttributeProgrammaticStreamSerialization;
    attrs[0].val.programmaticStreamSerializationAllowed = 1;
    cfg.attrs = attrs;
    cfg.numAttrs = 1;
    cudaError_t err = cudaLaunchKernelEx(&cfg, k_worker,
                                         tl_heat, br_heat, tl_off, br_off,
                                         tl_emb, br_emb, inp_h, inp_w, out);
    if (err != cudaSuccess) {
        k_worker<<<Bn, WT>>>(tl_heat, br_heat, tl_off, br_off,
                             tl_emb, br_emb, inp_h, inp_w, out);
    }
}